// round 17
// baseline (speedup 1.0000x reference)
#include <cuda_runtime.h>
#include <cuda_fp16.h>
#include <cstdint>

#define QSC 0.36067376022224085f   // 0.25 * log2(e)

__device__ __forceinline__ uint32_t s2u(const void* p) {
    uint32_t a;
    asm("{ .reg .u64 t; cvta.to.shared.u64 t, %1; cvt.u32.u64 %0, t; }" : "=r"(a) : "l"(p));
    return a;
}
__device__ __forceinline__ uint32_t pkh2(float hi, float lo) {
    uint32_t d;
    asm("cvt.rn.f16x2.f32 %0, %1, %2;" : "=r"(d) : "f"(hi), "f"(lo));
    return d;
}
__device__ __forceinline__ uint32_t ex2h2(uint32_t x) {
    uint32_t d;
    asm("ex2.approx.f16x2 %0, %1;" : "=r"(d) : "r"(x));
    return d;
}
#define LDSM4(r0, r1, r2, r3, a) \
    asm volatile("ldmatrix.sync.aligned.m8n8.x4.shared.b16 {%0,%1,%2,%3}, [%4];" \
        : "=r"(r0), "=r"(r1), "=r"(r2), "=r"(r3) : "r"(a))
#define MMA_F16(c, a, b0, b1) \
    asm volatile("mma.sync.aligned.m16n8k16.row.col.f32.f16.f16.f32 " \
        "{%0,%1,%2,%3},{%4,%5,%6,%7},{%8,%9},{%0,%1,%2,%3};" \
        : "+f"((c)[0]), "+f"((c)[1]), "+f"((c)[2]), "+f"((c)[3]) \
        : "r"((a)[0]), "r"((a)[1]), "r"((a)[2]), "r"((a)[3]), "r"(b0), "r"(b1))
#define MMA_F16C(c, a, b0, b1) \
    asm volatile("mma.sync.aligned.m16n8k16.row.col.f16.f16.f16.f16 " \
        "{%0,%1},{%2,%3,%4,%5},{%6,%7},{%0,%1};" \
        : "+r"((c)[0]), "+r"((c)[1]) \
        : "r"((a)[0]), "r"((a)[1]), "r"((a)[2]), "r"((a)[3]), "r"(b0), "r"(b1))

// CTA = one (window, head): 512 q x 512 k, 256 threads, 8 warps x 64 queries.
// grid = 1024, 2 CTAs/SM (independent barrier domains).
// smem (dynamic, 81920 B):
//  Ks @ 0     : 512 rows x 48B stride, f16 [16 dims]             (24 KB)
//  Vh @ 24576 : f16 transposed [16 dims][512 keys], swizzled      (16 KB)
//  Vf @ 40960 : f32 [512][16], 80B padded rows                    (40 KB)
//  Os @ 0     : overlay on Ks+Vh after mainloop, 512 x 80B        (40 KB)

extern "C" __global__ void __launch_bounds__(256, 2)
cssa_mma(const float* __restrict__ qkv, const float* __restrict__ wconv,
         const float* __restrict__ bconv, float* __restrict__ out)
{
    extern __shared__ char sm[];
    char* Ks = sm;
    char* Vh = sm + 24576;
    char* Vf = sm + 40960;
    char* Os = sm;
    __shared__ float wc[16][9];
    __shared__ float bc[16];

    const int blk = blockIdx.x;
    const int h = blk & 3, wi = blk >> 2, b = wi >> 3, wx = wi & 7;
    const int tid = threadIdx.x, lane = tid & 31, w = tid >> 5;

    const size_t bs = (size_t)4096 * 64;
    const float* qb = qkv + (size_t)b * bs + h * 16;
    const float* kb = qb + (size_t)32 * bs;
    const float* vb = kb + (size_t)32 * bs;

    if (tid < 144) wc[tid / 9][tid % 9] = wconv[(h * 16 + tid / 9) * 9 + tid % 9];
    if (tid < 16)  bc[tid] = bconv[h * 16 + tid];

    // ---------------- staging: K + V full window, 2 tokens/thread ----------------
    #pragma unroll
    for (int j = 0; j < 2; j++) {
        const int t = tid + j * 256;
        const int n = ((t >> 3) << 6) + (wx << 3) + (t & 7);
        const float4* kr = (const float4*)(kb + (size_t)n * 64);
        const float4* vr = (const float4*)(vb + (size_t)n * 64);
        uint32_t kh[8];
        #pragma unroll
        for (int c = 0; c < 4; c++) {
            const float4 k4 = kr[c];
            kh[c * 2 + 0] = pkh2(k4.y, k4.x);
            kh[c * 2 + 1] = pkh2(k4.w, k4.z);
            const float4 v4 = vr[c];
            *(float4*)(Vf + t * 80 + (c << 4)) = v4;
            const float e[4] = {v4.x, v4.y, v4.z, v4.w};
            #pragma unroll
            for (int jj = 0; jj < 4; jj++) {
                const int d = c * 4 + jj;
                *(__half*)(Vh + d * 1024 + (((t >> 3) ^ (d & 7)) << 4) + ((t & 7) << 1)) =
                    __float2half_rn(e[jj]);
            }
        }
        *(uint4*)(Ks + t * 48)      = make_uint4(kh[0], kh[1], kh[2], kh[3]);
        *(uint4*)(Ks + t * 48 + 16) = make_uint4(kh[4], kh[5], kh[6], kh[7]);
    }

    // ---------------- Q A-fragments direct from gmem (4 mt tiles) ----------------
    const int qbase = w * 64;
    uint32_t qf[4][4];
    {
        const int g  = lane >> 2;
        const int t2 = (lane & 3) * 2;
        #pragma unroll
        for (int mt = 0; mt < 4; mt++) {
            const int r0 = qbase + mt * 16 + g;
            #pragma unroll
            for (int half8 = 0; half8 < 2; half8++) {
                const int rq = r0 + half8 * 8;
                const int n  = ((rq >> 3) << 6) + (wx << 3) + (rq & 7);
                const float2 f0 = *(const float2*)(qb + (size_t)n * 64 + t2);
                const float2 f1 = *(const float2*)(qb + (size_t)n * 64 + 8 + t2);
                qf[mt][half8]     = pkh2(f0.y * QSC, f0.x * QSC);
                qf[mt][half8 + 2] = pkh2(f1.y * QSC, f1.x * QSC);
            }
        }
    }
    __syncthreads();

    // ---------------- main loop over 512 keys ----------------
    const uint32_t aK = s2u(Ks), aV = s2u(Vh);
    const int krow = (lane & 7) + ((lane >> 4) & 1) * 8;
    const int kseg = (lane >> 3) & 1;
    const uint32_t aKl = aK + krow * 48 + kseg * 16;

    const int vd = ((lane >> 4) & 1) * 8 + (lane & 7);
    const uint32_t aVd = aV + vd * 1024;
    const int vsw = (vd & 7) << 4;
    const int vm = ((lane >> 3) & 1) << 4;

    // per-mt ones-column B-fragments (col n = lane>>2): mt's rowsum lands in D col mt
    uint32_t onesb[4];
    #pragma unroll
    for (int mt = 0; mt < 4; mt++)
        onesb[mt] = ((lane >> 2) == mt) ? 0x3C003C00u : 0u;

    float O[4][2][4] = {};   // [mt][dims0-7 | dims8-15]
    float Or4[4] = {};       // SINGLE rowsum tile: D[r][mt] = rowsum of mt's query r

    #pragma unroll 2
    for (int nb = 0; nb < 32; nb++) {
        uint32_t kf[4], vf[4];
        LDSM4(kf[0], kf[1], kf[2], kf[3], aKl + nb * 768);
        LDSM4(vf[0], vf[1], vf[2], vf[3], aVd + (uint32_t)((nb * 32 + vm) ^ vsw));

        #pragma unroll
        for (int mt = 0; mt < 4; mt++) {
            uint32_t s0[2] = {0u, 0u}, s1[2] = {0u, 0u};
            MMA_F16C(s0, qf[mt], kf[0], kf[1]);   // keys 0-7
            MMA_F16C(s1, qf[mt], kf[2], kf[3]);   // keys 8-15
            uint32_t A[4];
            A[0] = ex2h2(s0[0]);
            A[1] = ex2h2(s0[1]);
            A[2] = ex2h2(s1[0]);
            A[3] = ex2h2(s1[1]);
            MMA_F16(O[mt][0], A, vf[0], vf[1]);
            MMA_F16(O[mt][1], A, vf[2], vf[3]);
            MMA_F16(Or4, A, onesb[mt], onesb[mt]);  // rowsum into shared tile, col mt
        }
    }

    // rowsum -> normalize: col mt at quad-slot mt>>1, reg c[mt&1] (row g) / c[2+(mt&1)] (row g+8)
    #pragma unroll
    for (int mt = 0; mt < 4; mt++) {
        const int src = (lane & ~3) | (mt >> 1);
        const float sg = __shfl_sync(0xFFFFFFFFu, Or4[mt & 1],       src);
        const float sh = __shfl_sync(0xFFFFFFFFu, Or4[2 + (mt & 1)], src);
        const float ig = 1.0f / sg, ih = 1.0f / sh;
        #pragma unroll
        for (int vt = 0; vt < 2; vt++) {
            O[mt][vt][0] *= ig; O[mt][vt][1] *= ig;
            O[mt][vt][2] *= ih; O[mt][vt][3] *= ih;
        }
    }

    __syncthreads();   // all warps done reading Ks/Vh (Os overlays them)

    #pragma unroll
    for (int mt = 0; mt < 4; mt++)
        #pragma unroll
        for (int vt = 0; vt < 2; vt++) {
            const int r0 = qbase + mt * 16 + (lane >> 2);
            const int cb = (vt * 8 + (lane & 3) * 2) * 4;
            *(float2*)(Os + r0 * 80 + cb)       = make_float2(O[mt][vt][0], O[mt][vt][1]);
            *(float2*)(Os + (r0 + 8) * 80 + cb) = make_float2(O[mt][vt][2], O[mt][vt][3]);
        }
    __syncthreads();

    // ---------------- epilogue: 2 queries/thread (LePE from smem Vf) ----------------
    #pragma unroll
    for (int j = 0; j < 2; j++) {
        const int t = tid + j * 256, y = t >> 3, x = t & 7;
        float o[16];
        #pragma unroll
        for (int c = 0; c < 4; c++) {
            const float4 f = *(const float4*)(Os + t * 80 + c * 16);
            o[c * 4] = f.x; o[c * 4 + 1] = f.y; o[c * 4 + 2] = f.z; o[c * 4 + 3] = f.w;
        }
        #pragma unroll
        for (int d = 0; d < 16; d++) o[d] += bc[d];

        #pragma unroll
        for (int dy = -1; dy <= 1; dy++) {
            const int yy = y + dy;
            if ((unsigned)yy >= 64u) continue;
            #pragma unroll
            for (int dx = -1; dx <= 1; dx++) {
                const int xx = x + dx;
                if ((unsigned)xx >= 8u) continue;
                const char* vrow = Vf + (yy * 8 + xx) * 80;
                const int widx = (dy + 1) * 3 + (dx + 1);
                #pragma unroll
                for (int c = 0; c < 4; c++) {
                    const float4 v = *(const float4*)(vrow + c * 16);
                    o[c * 4]     += wc[c * 4][widx] * v.x;
                    o[c * 4 + 1] += wc[c * 4 + 1][widx] * v.y;
                    o[c * 4 + 2] += wc[c * 4 + 2][widx] * v.z;
                    o[c * 4 + 3] += wc[c * 4 + 3][widx] * v.w;
                }
            }
        }
        const int n = (y << 6) + (wx << 3) + x;
        float4* dst = (float4*)(out + ((size_t)b * 4096 + n) * 64 + h * 16);
        #pragma unroll
        for (int c = 0; c < 4; c++)
            dst[c] = make_float4(o[c * 4], o[c * 4 + 1], o[c * 4 + 2], o[c * 4 + 3]);
    }
}

extern "C" void kernel_launch(void* const* d_in, const int* in_sizes, int n_in,
                              void* d_out, int out_size) {
    const float* qkv = (const float*)d_in[0];
    const float* wconv = (const float*)d_in[1];
    const float* bconv = (const float*)d_in[2];
    float* out = (float*)d_out;
    const int smem_bytes = 81920;
    cudaFuncSetAttribute(cssa_mma, cudaFuncAttributeMaxDynamicSharedMemorySize, smem_bytes);
    cssa_mma<<<1024, 256, smem_bytes>>>(qkv, wconv, bconv, out);
}